// round 15
// baseline (speedup 1.0000x reference)
#include <cuda_runtime.h>
#include <math.h>

// Shape (fixed by the dataset)
#define NB 8
#define NT 4096
#define NH 8
#define ND 64
#define DQ 16                 // float4 lanes over D
#define L 8                   // timesteps per thread
#define SUBS 32               // sub-chunks per tile (block = SUBS*DQ = 512 threads)
#define TILE_T (L * SUBS)     // 256 timesteps per tile
#define NTILES (NT / TILE_T)  // 16  (<= 32: lookback fits in one warp)
#define NBH (NB * NH)         // 64
#define NBLK (NTILES * NBH)   // 1024
#define NFLAG (NTILES * NBH * DQ)
#define F4T (NH * ND / 4)     // float4 stride between consecutive t = 128
#define SMP 17                // padded smem stride (float4 units)
#define FULLM 0xFFFFFFFFu

// Aggregate-only lookback state. Zero-initialized at module load; the last
// finished block of every launch resets it for the next graph replay.
__device__ float4 g_S[NFLAG];        // tile aggregates
__device__ int    g_flag[NFLAG];     // 0 = empty, 1 = aggregate ready
__device__ int    g_done;            // finished-block counter

static __device__ __forceinline__ void st_release(int* p, int v) {
    asm volatile("st.release.gpu.s32 [%0], %1;" :: "l"(p), "r"(v) : "memory");
}
static __device__ __forceinline__ int ld_acquire(const int* p) {
    int v;
    asm volatile("ld.acquire.gpu.s32 %0, [%1];" : "=r"(v) : "l"(p) : "memory");
    return v;
}
static __device__ __forceinline__ float4 fma4(float s, float4 A, float4 B) {
    return make_float4(fmaf(s, A.x, B.x), fmaf(s, A.y, B.y),
                       fmaf(s, A.z, B.z), fmaf(s, A.w, B.w));
}

__global__ __launch_bounds__(512, 2) void k_scan(
    const float4* __restrict__ v, const float4* __restrict__ x,
    const float4* __restrict__ v0, const float* __restrict__ sw,
    float4* __restrict__ out)
{
    __shared__ float4 smT[SUBS * SMP];   // aggregates -> exclusive prefixes (padded)
    __shared__ float4 carry_sm[DQ];
    __shared__ int    is_last;

    const int tid  = threadIdx.x;
    const int dq   = tid & 15;
    const int sub  = tid >> 4;
    const int wid  = tid >> 5;          // warp id == dq owned in phases B/C
    const int lane = tid & 31;
    const int bh   = blockIdx.x;        // channel fastest -> tile-major waves
    const int tile = blockIdx.y;
    const int h    = bh & (NH - 1);
    const int b    = bh >> 3;

    const float a  = 1.0f / (1.0f + expf(-sw[h]));
    const float om = 1.0f - a;
    const float cf = a * (om / fmaxf(om, 1e-6f));
    float a8_1 = a;
    #pragma unroll
    for (int i = 0; i < 3; ++i) a8_1 *= a8_1;          // a^8
    const float a8_2  = a8_1 * a8_1;                   // a^16
    const float a8_4  = a8_2 * a8_2;                   // a^32
    const float a8_8  = a8_4 * a8_4;                   // a^64
    const float a8_16 = a8_8 * a8_8;                   // a^128
    const float aT    = a8_16 * a8_16;                 // a^256 = a^TILE_T

    const int base = ((b * NT + tile * TILE_T + sub * L) * NH + h) * (ND / 4) + dq;

    // ---- phase A: local scan of L steps (zero-seeded) in registers ----
    float4 y[L];
    float4 yy = make_float4(0.f, 0.f, 0.f, 0.f);
    #pragma unroll
    for (int i = 0; i < L; ++i) {
        float4 vv = v[base + i * F4T];
        float4 xx = x[base + i * F4T];
        yy.x = fmaf(a, yy.x, fmaf(om, vv.x, cf * xx.x));
        yy.y = fmaf(a, yy.y, fmaf(om, vv.y, cf * xx.y));
        yy.z = fmaf(a, yy.z, fmaf(om, vv.z, cf * xx.z));
        yy.w = fmaf(a, yy.w, fmaf(om, vv.w, cf * xx.w));
        y[i] = yy;
    }
    smT[sub * SMP + dq] = yy;
    __syncthreads();

    // ---- phase B: warp wid KS-scans the 32 sub-aggregates of dq == wid ----
    // I_s = sum_{k<=s} a8^(s-k) S_k   (weighted Kogge-Stone, validated R7/R11)
    float4 I = smT[lane * SMP + wid];
    {
        float f = a8_1;
        #pragma unroll
        for (int o = 1; o < 32; o <<= 1) {
            float4 t;
            t.x = __shfl_up_sync(FULLM, I.x, o);
            t.y = __shfl_up_sync(FULLM, I.y, o);
            t.z = __shfl_up_sync(FULLM, I.z, o);
            t.w = __shfl_up_sync(FULLM, I.w, o);
            if (lane >= o) I = fma4(f, t, I);
            f *= f;
        }
    }
    const int sidx = (tile * NBH + bh) * DQ + wid;
    // publish tile aggregate IMMEDIATELY (lane 31 holds the inclusive total)
    if (lane == 31) {
        __stcg(&g_S[sidx], I);
        st_release(&g_flag[sidx], 1);
    }
    // exclusive prefix: entry state of sub-chunk s (zero tile seed) = I_{s-1}
    float4 E;
    E.x = __shfl_up_sync(FULLM, I.x, 1);
    E.y = __shfl_up_sync(FULLM, I.y, 1);
    E.z = __shfl_up_sync(FULLM, I.z, 1);
    E.w = __shfl_up_sync(FULLM, I.w, 1);
    if (lane == 0) E = make_float4(0.f, 0.f, 0.f, 0.f);
    smT[lane * SMP + wid] = E;

    // ---- phase C: aggregate-only parallel lookback (no P-chain) ----
    // carry_t = sum_{k<t} aT^k S[t-1-k]  +  aT^t v0     (lane k handles hop k)
    float4 val = make_float4(0.f, 0.f, 0.f, 0.f);
    {
        const float aT2 = aT * aT, aT4 = aT2 * aT2, aT8 = aT4 * aT4, aT16 = aT8 * aT8;
        float dj = 1.0f;                 // aT^lane from bits (exact products)
        if (lane & 1)  dj *= aT;
        if (lane & 2)  dj *= aT2;
        if (lane & 4)  dj *= aT4;
        if (lane & 8)  dj *= aT8;
        if (lane & 16) dj *= aT16;
        if (lane < tile) {
            const int pidx = ((tile - 1 - lane) * NBH + bh) * DQ + wid;
            while (ld_acquire(&g_flag[pidx]) == 0) __nanosleep(40);
            val = fma4(dj, __ldcg(&g_S[pidx]), val);
        } else if (lane == tile) {
            val = fma4(dj, __ldg(&v0[h * DQ + wid]), val);
        }
        __syncwarp(FULLM);
        #pragma unroll
        for (int o = 16; o >= 1; o >>= 1) {
            val.x += __shfl_xor_sync(FULLM, val.x, o);
            val.y += __shfl_xor_sync(FULLM, val.y, o);
            val.z += __shfl_xor_sync(FULLM, val.z, o);
            val.w += __shfl_xor_sync(FULLM, val.w, o);
        }
    }
    if (lane == 0) carry_sm[wid] = val;
    __syncthreads();

    // ---- phase D: apply carry in registers, single store pass ----
    const float4 carry = carry_sm[dq];
    const float4 E2 = smT[sub * SMP + dq];
    float p = 1.0f;                      // a8^sub from bits (exact products)
    if (sub & 1)  p *= a8_1;
    if (sub & 2)  p *= a8_2;
    if (sub & 4)  p *= a8_4;
    if (sub & 8)  p *= a8_8;
    if (sub & 16) p *= a8_16;
    const float4 c = fma4(p, carry, E2);

    float pa = a;
    #pragma unroll
    for (int i = 0; i < L; ++i) {
        out[base + i * F4T] = fma4(pa, c, y[i]);
        pa *= a;
    }

    // ---- last finished block resets lookback state for the next graph replay ----
    __threadfence();
    if (tid == 0) is_last = (atomicAdd(&g_done, 1) == NBLK - 1);
    __syncthreads();
    if (is_last) {
        for (int i = tid; i < NFLAG; i += 512) g_flag[i] = 0;
        if (tid == 0) g_done = 0;
    }
}

extern "C" void kernel_launch(void* const* d_in, const int* in_sizes, int n_in,
                              void* d_out, int out_size)
{
    const float4* v  = (const float4*)d_in[0];   // values   [B,T,H,D] f32
    const float4* x  = (const float4*)d_in[1];   // aux      [B,T,H,D] f32
    const float4* v0 = (const float4*)d_in[2];   // v0       [1,1,H,D] f32
    const float*  sw = (const float*)d_in[3];    // weight   [H,1]     f32

    k_scan<<<dim3(NBH, NTILES), SUBS * DQ>>>(v, x, (const float4*)v0, sw, (float4*)d_out);
}

// round 17
// speedup vs baseline: 1.1604x; 1.1604x over previous
#include <cuda_runtime.h>
#include <math.h>

// Shape (fixed by the dataset)
#define NB 8
#define NT 4096
#define NH 8
#define ND 64
#define DQ 16                 // float4 lanes over D
#define L 8                   // timesteps per thread
#define SUBS 32               // sub-chunks per tile (block = SUBS*DQ = 512 threads)
#define TILE_T (L * SUBS)     // 256 timesteps per tile
#define NTILES (NT / TILE_T)  // 16  (<= 32: lookback fits in one warp)
#define NBH (NB * NH)         // 64
#define NBLK (NTILES * NBH)   // 1024
#define NFLAG (NTILES * NBH * DQ)
#define F4T (NH * ND / 4)     // float4 stride between consecutive t = 128
#define SMP 17                // padded smem stride (float4 units)
#define FULLM 0xFFFFFFFFu

// Aggregate-only lookback state. Monotonic epoch protocol: a flag is "ready"
// iff it equals this launch's epoch; stale flags from earlier launches are
// strictly smaller, so no reset pass is ever needed. Launches are stream-
// ordered by the harness, so g_done is always 0 at launch entry and the
// epoch bump happens strictly between launches.
__device__ float4 g_S[NFLAG];        // tile aggregates
__device__ int    g_flag[NFLAG];     // == epoch when ready
__device__ int    g_epoch = 1;       // current launch's epoch (bumped at tail)
__device__ int    g_done;            // finished-block counter

static __device__ __forceinline__ void st_release(int* p, int v) {
    asm volatile("st.release.gpu.s32 [%0], %1;" :: "l"(p), "r"(v) : "memory");
}
static __device__ __forceinline__ int ld_acquire(const int* p) {
    int v;
    asm volatile("ld.acquire.gpu.s32 %0, [%1];" : "=r"(v) : "l"(p) : "memory");
    return v;
}
static __device__ __forceinline__ float4 fma4(float s, float4 A, float4 B) {
    return make_float4(fmaf(s, A.x, B.x), fmaf(s, A.y, B.y),
                       fmaf(s, A.z, B.z), fmaf(s, A.w, B.w));
}

__global__ __launch_bounds__(512, 2) void k_scan(
    const float4* __restrict__ v, const float4* __restrict__ x,
    const float4* __restrict__ v0, const float* __restrict__ sw,
    float4* __restrict__ out)
{
    __shared__ float4 smT[SUBS * SMP];   // aggregates -> exclusive prefixes (padded)
    __shared__ float4 carry_sm[DQ];

    const int tid  = threadIdx.x;
    const int dq   = tid & 15;
    const int sub  = tid >> 4;
    const int wid  = tid >> 5;          // warp id == dq owned in phases B/C
    const int lane = tid & 31;
    const int bh   = blockIdx.x;        // channel fastest -> tile-major waves
    const int tile = blockIdx.y;
    const int h    = bh & (NH - 1);
    const int b    = bh >> 3;

    const int epoch = g_epoch;          // constant for the whole launch
                                        // (every block reads BEFORE its g_done
                                        //  increment, so the bump is never
                                        //  visible mid-launch)

    const float a  = 1.0f / (1.0f + expf(-sw[h]));
    const float om = 1.0f - a;
    const float cf = a * (om / fmaxf(om, 1e-6f));
    float a8_1 = a;
    #pragma unroll
    for (int i = 0; i < 3; ++i) a8_1 *= a8_1;          // a^8
    const float a8_2  = a8_1 * a8_1;                   // a^16
    const float a8_4  = a8_2 * a8_2;                   // a^32
    const float a8_8  = a8_4 * a8_4;                   // a^64
    const float a8_16 = a8_8 * a8_8;                   // a^128
    const float aT    = a8_16 * a8_16;                 // a^256 = a^TILE_T

    const int base = ((b * NT + tile * TILE_T + sub * L) * NH + h) * (ND / 4) + dq;

    // ---- phase A: local scan of L steps (zero-seeded) in registers ----
    float4 y[L];
    float4 yy = make_float4(0.f, 0.f, 0.f, 0.f);
    #pragma unroll
    for (int i = 0; i < L; ++i) {
        float4 vv = v[base + i * F4T];
        float4 xx = x[base + i * F4T];
        yy.x = fmaf(a, yy.x, fmaf(om, vv.x, cf * xx.x));
        yy.y = fmaf(a, yy.y, fmaf(om, vv.y, cf * xx.y));
        yy.z = fmaf(a, yy.z, fmaf(om, vv.z, cf * xx.z));
        yy.w = fmaf(a, yy.w, fmaf(om, vv.w, cf * xx.w));
        y[i] = yy;
    }
    smT[sub * SMP + dq] = yy;
    __syncthreads();

    // ---- phase B: warp wid KS-scans the 32 sub-aggregates of dq == wid ----
    // I_s = sum_{k<=s} a8^(s-k) S_k   (weighted Kogge-Stone, validated R7/R11)
    float4 I = smT[lane * SMP + wid];
    {
        float f = a8_1;
        #pragma unroll
        for (int o = 1; o < 32; o <<= 1) {
            float4 t;
            t.x = __shfl_up_sync(FULLM, I.x, o);
            t.y = __shfl_up_sync(FULLM, I.y, o);
            t.z = __shfl_up_sync(FULLM, I.z, o);
            t.w = __shfl_up_sync(FULLM, I.w, o);
            if (lane >= o) I = fma4(f, t, I);
            f *= f;
        }
    }
    const int sidx = (tile * NBH + bh) * DQ + wid;
    // publish tile aggregate IMMEDIATELY (lane 31 holds the inclusive total)
    if (lane == 31) {
        __stcg(&g_S[sidx], I);
        st_release(&g_flag[sidx], epoch);
    }
    // exclusive prefix: entry state of sub-chunk s (zero tile seed) = I_{s-1}
    float4 E;
    E.x = __shfl_up_sync(FULLM, I.x, 1);
    E.y = __shfl_up_sync(FULLM, I.y, 1);
    E.z = __shfl_up_sync(FULLM, I.z, 1);
    E.w = __shfl_up_sync(FULLM, I.w, 1);
    if (lane == 0) E = make_float4(0.f, 0.f, 0.f, 0.f);
    smT[lane * SMP + wid] = E;

    // ---- phase C: aggregate-only parallel lookback (no P-chain) ----
    // carry_t = sum_{k<t} aT^k S[t-1-k]  +  aT^t v0     (lane k handles hop k)
    float4 val = make_float4(0.f, 0.f, 0.f, 0.f);
    {
        const float aT2 = aT * aT, aT4 = aT2 * aT2, aT8 = aT4 * aT4, aT16 = aT8 * aT8;
        float dj = 1.0f;                 // aT^lane from bits (exact products)
        if (lane & 1)  dj *= aT;
        if (lane & 2)  dj *= aT2;
        if (lane & 4)  dj *= aT4;
        if (lane & 8)  dj *= aT8;
        if (lane & 16) dj *= aT16;
        if (lane < tile) {
            const int pidx = ((tile - 1 - lane) * NBH + bh) * DQ + wid;
            while (ld_acquire(&g_flag[pidx]) != epoch) __nanosleep(40);
            val = fma4(dj, __ldcg(&g_S[pidx]), val);
        } else if (lane == tile) {
            val = fma4(dj, __ldg(&v0[h * DQ + wid]), val);
        }
        __syncwarp(FULLM);
        #pragma unroll
        for (int o = 16; o >= 1; o >>= 1) {
            val.x += __shfl_xor_sync(FULLM, val.x, o);
            val.y += __shfl_xor_sync(FULLM, val.y, o);
            val.z += __shfl_xor_sync(FULLM, val.z, o);
            val.w += __shfl_xor_sync(FULLM, val.w, o);
        }
    }
    if (lane == 0) carry_sm[wid] = val;
    __syncthreads();

    // ---- phase D: apply carry in registers, single store pass ----
    const float4 carry = carry_sm[dq];
    const float4 E2 = smT[sub * SMP + dq];
    float p = 1.0f;                      // a8^sub from bits (exact products)
    if (sub & 1)  p *= a8_1;
    if (sub & 2)  p *= a8_2;
    if (sub & 4)  p *= a8_4;
    if (sub & 8)  p *= a8_8;
    if (sub & 16) p *= a8_16;
    const float4 c = fma4(p, carry, E2);

    float pa = a;
    #pragma unroll
    for (int i = 0; i < L; ++i) {
        out[base + i * F4T] = fma4(pa, c, y[i]);
        pa *= a;
    }

    // ---- tail: thread 0 only; last finisher advances the epoch ----
    // No fence: the bump guards nothing inside this launch (spinners compare
    // against their pre-loaded epoch; flag/S ordering is via st_release), and
    // cross-launch visibility comes from the kernel boundary.
    if (tid == 0) {
        if (atomicAdd(&g_done, 1) == NBLK - 1) {
            g_done  = 0;
            g_epoch = epoch + 1;
        }
    }
}

extern "C" void kernel_launch(void* const* d_in, const int* in_sizes, int n_in,
                              void* d_out, int out_size)
{
    const float4* v  = (const float4*)d_in[0];   // values   [B,T,H,D] f32
    const float4* x  = (const float4*)d_in[1];   // aux      [B,T,H,D] f32
    const float4* v0 = (const float4*)d_in[2];   // v0       [1,1,H,D] f32
    const float*  sw = (const float*)d_in[3];    // weight   [H,1]     f32

    k_scan<<<dim3(NBH, NTILES), SUBS * DQ>>>(v, x, (const float4*)v0, sw, (float4*)d_out);
}